// round 1
// baseline (speedup 1.0000x reference)
#include <cuda_runtime.h>
#include <cuda_bf16.h>
#include <cstdint>

#define N_NODES 50000
#define N_EDGES 600000
#define FEAT    128
#define N_CLS   40

// ---------------- scratch (no allocations allowed) ----------------
__device__ float g_deg[N_NODES];            // degree, then 1/max(deg,1)
__device__ float g_agg[N_NODES * FEAT];     // scatter-add accumulator
__device__ float g_h1[N_NODES * FEAT];
__device__ float g_h2[N_NODES * FEAT];
__device__ float g_h3[N_NODES * FEAT];

// ---------------- small utility kernels ----------------
__global__ void zero_buf(float4* __restrict__ p, int n4) {
    int i = blockIdx.x * blockDim.x + threadIdx.x;
    if (i < n4) p[i] = make_float4(0.f, 0.f, 0.f, 0.f);
}

__global__ void deg_count(const int* __restrict__ dst) {
    int e = blockIdx.x * blockDim.x + threadIdx.x;
    if (e < N_EDGES) atomicAdd(&g_deg[dst[e]], 1.0f);
}

__global__ void deg_invert() {
    int i = blockIdx.x * blockDim.x + threadIdx.x;
    if (i < N_NODES) g_deg[i] = 1.0f / fmaxf(g_deg[i], 1.0f);
}

// ---------------- edge scatter-add (mean-agg numerator) ----------------
// one warp per edge: 32 lanes x float4 = 512B row; vector RED to L2.
__global__ __launch_bounds__(256)
void scatter_add(const float* __restrict__ X,
                 const int* __restrict__ src,
                 const int* __restrict__ dst) {
    int idx  = blockIdx.x * blockDim.x + threadIdx.x;
    int e    = idx >> 5;
    int lane = idx & 31;
    if (e >= N_EDGES) return;
    int s = __ldg(src + e);
    int d = __ldg(dst + e);
    float4 v = __ldg(reinterpret_cast<const float4*>(X + (size_t)s * FEAT) + lane);
    float* o = g_agg + (size_t)d * FEAT + (size_t)lane * 4;
    asm volatile("red.global.add.v4.f32 [%0], {%1,%2,%3,%4};"
                 :: "l"(o), "f"(v.x), "f"(v.y), "f"(v.z), "f"(v.w) : "memory");
}

// ---------------- fused SAGE layer GEMM ----------------
// out[m,n] = relu( (agg[m,:]*dinv[m]) . Wl[n,:] + x[m,:] . Wr[n,:] + bl[n] ) (+ res[m,n])
// BM=64 rows, BN=128 cols, K=128, two K-passes (Wl then Wr) into the same acc.
// 256 threads, each computes 4 rows x 8 cols (cols strided by 16 for bank-free smem reads).
#define PAD 129
#define SMEM_GEMM ((64 * PAD + 128 * PAD) * (int)sizeof(float))

__global__ __launch_bounds__(256)
void sage_gemm(const float* __restrict__ Ain,   // unscaled aggregate
               const float* __restrict__ Xin,   // root features
               const float* __restrict__ dinv,
               const float* __restrict__ Wl,
               const float* __restrict__ bl,
               const float* __restrict__ Wr,
               const float* __restrict__ res,   // may be null
               float* __restrict__ out) {
    extern __shared__ float sm[];
    float* sA = sm;              // [64][PAD]
    float* sW = sm + 64 * PAD;   // [128][PAD]

    const int tid  = threadIdx.x;
    const int warp = tid >> 5;
    const int lane = tid & 31;
    const int tx   = tid & 15;   // 16 col-groups
    const int ty   = tid >> 4;   // 16 row-groups
    const int m0   = blockIdx.x * 64;

    float acc[4][8];
#pragma unroll
    for (int r = 0; r < 4; r++)
#pragma unroll
        for (int c = 0; c < 8; c++) acc[r][c] = 0.f;

    for (int pass = 0; pass < 2; ++pass) {
        const float* A = pass ? Xin : Ain;
        const float* W = pass ? Wr  : Wl;
        if (pass) __syncthreads();   // protect smem from previous pass readers

        // stage A tile (scaled by deg_inv on the aggregate pass)
        for (int r = warp; r < 64; r += 8) {
            int m = m0 + r;
            float4 v = make_float4(0.f, 0.f, 0.f, 0.f);
            float s = 1.f;
            if (m < N_NODES) {
                v = __ldg(reinterpret_cast<const float4*>(A + (size_t)m * FEAT) + lane);
                if (pass == 0) s = __ldg(dinv + m);
            }
            float* row = sA + r * PAD + lane * 4;
            row[0] = v.x * s; row[1] = v.y * s; row[2] = v.z * s; row[3] = v.w * s;
        }
        // stage W tile
        for (int n = warp; n < 128; n += 8) {
            float4 v = __ldg(reinterpret_cast<const float4*>(W + (size_t)n * FEAT) + lane);
            float* row = sW + n * PAD + lane * 4;
            row[0] = v.x; row[1] = v.y; row[2] = v.z; row[3] = v.w;
        }
        __syncthreads();

#pragma unroll 4
        for (int k = 0; k < 128; k++) {
            float a[4], w[8];
#pragma unroll
            for (int r = 0; r < 4; r++) a[r] = sA[(ty * 4 + r) * PAD + k];
#pragma unroll
            for (int c = 0; c < 8; c++) w[c] = sW[(tx + 16 * c) * PAD + k];
#pragma unroll
            for (int r = 0; r < 4; r++)
#pragma unroll
                for (int c = 0; c < 8; c++)
                    acc[r][c] = fmaf(a[r], w[c], acc[r][c]);
        }
    }

    // epilogue: bias + relu (+ residual)
#pragma unroll
    for (int r = 0; r < 4; r++) {
        int m = m0 + ty * 4 + r;
        if (m < N_NODES) {
#pragma unroll
            for (int c = 0; c < 8; c++) {
                int n = tx + 16 * c;
                float v = acc[r][c] + __ldg(bl + n);
                v = fmaxf(v, 0.f);
                if (res) v += __ldg(res + (size_t)m * FEAT + n);
                out[(size_t)m * FEAT + n] = v;
            }
        }
    }
}

// ---------------- classifier: out[m,c] = vif[m,:] . Wc[c,:] + bc[c] ----------------
// BM=128 rows, 40 cols. 256 threads: 32 row-groups x 8 col-groups, 4x5 per thread.
#define SMEM_CLS ((128 * PAD + 40 * PAD) * (int)sizeof(float))

__global__ __launch_bounds__(256)
void classifier_k(const float* __restrict__ X,
                  const float* __restrict__ Wc,
                  const float* __restrict__ bc,
                  float* __restrict__ out) {
    extern __shared__ float sm[];
    float* sX = sm;               // [128][PAD]
    float* sW = sm + 128 * PAD;   // [40][PAD]

    const int tid  = threadIdx.x;
    const int warp = tid >> 5;
    const int lane = tid & 31;
    const int tx   = tid & 7;     // 8 col-groups
    const int ty   = tid >> 3;    // 32 row-groups
    const int m0   = blockIdx.x * 128;

    for (int r = warp; r < 128; r += 8) {
        int m = m0 + r;
        float4 v = make_float4(0.f, 0.f, 0.f, 0.f);
        if (m < N_NODES)
            v = __ldg(reinterpret_cast<const float4*>(X + (size_t)m * FEAT) + lane);
        float* row = sX + r * PAD + lane * 4;
        row[0] = v.x; row[1] = v.y; row[2] = v.z; row[3] = v.w;
    }
    for (int n = warp; n < N_CLS; n += 8) {
        float4 v = __ldg(reinterpret_cast<const float4*>(Wc + (size_t)n * FEAT) + lane);
        float* row = sW + n * PAD + lane * 4;
        row[0] = v.x; row[1] = v.y; row[2] = v.z; row[3] = v.w;
    }
    __syncthreads();

    float acc[4][5];
#pragma unroll
    for (int r = 0; r < 4; r++)
#pragma unroll
        for (int c = 0; c < 5; c++) acc[r][c] = 0.f;

#pragma unroll 4
    for (int k = 0; k < 128; k++) {
        float a[4], w[5];
#pragma unroll
        for (int r = 0; r < 4; r++) a[r] = sX[(ty * 4 + r) * PAD + k];
#pragma unroll
        for (int c = 0; c < 5; c++) w[c] = sW[(tx + 8 * c) * PAD + k];
#pragma unroll
        for (int r = 0; r < 4; r++)
#pragma unroll
            for (int c = 0; c < 5; c++)
                acc[r][c] = fmaf(a[r], w[c], acc[r][c]);
    }

#pragma unroll
    for (int r = 0; r < 4; r++) {
        int m = m0 + ty * 4 + r;
        if (m < N_NODES) {
#pragma unroll
            for (int c = 0; c < 5; c++) {
                int n = tx + 8 * c;   // 0..39
                out[(size_t)m * N_CLS + n] = acc[r][c] + __ldg(bc + n);
            }
        }
    }
}

// ---------------- launch ----------------
extern "C" void kernel_launch(void* const* d_in, const int* in_sizes, int n_in,
                              void* d_out, int out_size) {
    const float* x   = (const float*)d_in[0];
    const int*   ei  = (const int*)d_in[1];
    const float* Wl1 = (const float*)d_in[2];
    const float* bl1 = (const float*)d_in[3];
    const float* Wr1 = (const float*)d_in[4];
    const float* Wl2 = (const float*)d_in[5];
    const float* bl2 = (const float*)d_in[6];
    const float* Wr2 = (const float*)d_in[7];
    const float* Wl3 = (const float*)d_in[8];
    const float* bl3 = (const float*)d_in[9];
    const float* Wr3 = (const float*)d_in[10];
    const float* Wc  = (const float*)d_in[11];
    const float* bc  = (const float*)d_in[12];
    float* out = (float*)d_out;

    const int* src = ei;
    const int* dst = ei + N_EDGES;

    float *p_deg, *p_agg, *p_h1, *p_h2, *p_h3;
    cudaGetSymbolAddress((void**)&p_deg, g_deg);
    cudaGetSymbolAddress((void**)&p_agg, g_agg);
    cudaGetSymbolAddress((void**)&p_h1,  g_h1);
    cudaGetSymbolAddress((void**)&p_h2,  g_h2);
    cudaGetSymbolAddress((void**)&p_h3,  g_h3);

    cudaFuncSetAttribute(sage_gemm,    cudaFuncAttributeMaxDynamicSharedMemorySize, SMEM_GEMM);
    cudaFuncSetAttribute(classifier_k, cudaFuncAttributeMaxDynamicSharedMemorySize, SMEM_CLS);

    const int AGG4 = N_NODES * FEAT / 4;   // 1.6M float4
    const int DEG4 = N_NODES / 4;          // 12.5K float4
    const int scatter_blocks = (N_EDGES * 32 + 255) / 256;
    const int gemm_blocks    = (N_NODES + 63) / 64;
    const int cls_blocks     = (N_NODES + 127) / 128;

    // degree + inverse
    zero_buf<<<(DEG4 + 255) / 256, 256>>>((float4*)p_deg, DEG4);
    deg_count<<<(N_EDGES + 255) / 256, 256>>>(dst);
    deg_invert<<<(N_NODES + 255) / 256, 256>>>();

    // layer 1
    zero_buf<<<(AGG4 + 255) / 256, 256>>>((float4*)p_agg, AGG4);
    scatter_add<<<scatter_blocks, 256>>>(x, src, dst);
    sage_gemm<<<gemm_blocks, 256, SMEM_GEMM>>>(p_agg, x, p_deg, Wl1, bl1, Wr1, nullptr, p_h1);

    // layer 2
    zero_buf<<<(AGG4 + 255) / 256, 256>>>((float4*)p_agg, AGG4);
    scatter_add<<<scatter_blocks, 256>>>(p_h1, src, dst);
    sage_gemm<<<gemm_blocks, 256, SMEM_GEMM>>>(p_agg, p_h1, p_deg, Wl2, bl2, Wr2, nullptr, p_h2);

    // layer 3 + residual (vanilla_if)
    zero_buf<<<(AGG4 + 255) / 256, 256>>>((float4*)p_agg, AGG4);
    scatter_add<<<scatter_blocks, 256>>>(p_h2, src, dst);
    sage_gemm<<<gemm_blocks, 256, SMEM_GEMM>>>(p_agg, p_h2, p_deg, Wl3, bl3, Wr3, p_h2, p_h3);

    // classifier
    classifier_k<<<cls_blocks, 256, SMEM_CLS>>>(p_h3, Wc, bc, out);
}

// round 3
// speedup vs baseline: 1.4275x; 1.4275x over previous
#include <cuda_runtime.h>
#include <cuda_bf16.h>
#include <cstdint>

#define N_NODES 50000
#define N_EDGES 600000
#define FEAT    128
#define N_CLS   40

// ---------------- scratch (no allocations allowed) ----------------
__device__ float g_deg[N_NODES];
__device__ float g_agg[N_NODES * FEAT];
__device__ float g_h1[N_NODES * FEAT];
__device__ float g_h2[N_NODES * FEAT];
__device__ float g_h3[N_NODES * FEAT];

// ---------------- small utility kernels ----------------
__global__ void zero_buf(float4* __restrict__ p, int n4) {
    int i = blockIdx.x * blockDim.x + threadIdx.x;
    if (i < n4) p[i] = make_float4(0.f, 0.f, 0.f, 0.f);
}

__global__ void deg_count(const int* __restrict__ dst) {
    int e = blockIdx.x * blockDim.x + threadIdx.x;
    if (e < N_EDGES) atomicAdd(&g_deg[dst[e]], 1.0f);
}

__global__ void deg_invert() {
    int i = blockIdx.x * blockDim.x + threadIdx.x;
    if (i < N_NODES) g_deg[i] = 1.0f / fmaxf(g_deg[i], 1.0f);
}

// ---------------- edge scatter-add ----------------
__global__ __launch_bounds__(256)
void scatter_add(const float* __restrict__ X,
                 const int* __restrict__ src,
                 const int* __restrict__ dst) {
    int idx  = blockIdx.x * blockDim.x + threadIdx.x;
    int e    = idx >> 5;
    int lane = idx & 31;
    if (e >= N_EDGES) return;
    int s = __ldg(src + e);
    int d = __ldg(dst + e);
    float4 v = __ldg(reinterpret_cast<const float4*>(X + (size_t)s * FEAT) + lane);
    float* o = g_agg + (size_t)d * FEAT + (size_t)lane * 4;
    asm volatile("red.global.add.v4.f32 [%0], {%1,%2,%3,%4};"
                 :: "l"(o), "f"(v.x), "f"(v.y), "f"(v.z), "f"(v.w) : "memory");
}

// ---------------- mma.sync bf16 (baseline PTX, works on compute_103) ----------------
__device__ __forceinline__ void mma_bf16(float* c, const uint32_t* a, const uint32_t* b) {
    asm volatile(
        "mma.sync.aligned.m16n8k16.row.col.f32.bf16.bf16.f32 "
        "{%0,%1,%2,%3}, {%4,%5,%6,%7}, {%8,%9}, {%0,%1,%2,%3};"
        : "+f"(c[0]), "+f"(c[1]), "+f"(c[2]), "+f"(c[3])
        : "r"(a[0]), "r"(a[1]), "r"(a[2]), "r"(a[3]), "r"(b[0]), "r"(b[1]));
}

// ---------------- fp32 -> split bf16 (hi/lo) staging into padded smem ----------------
// smem layout: row-major, 128 rows, stride 136 bf16 elements (272B, 16B aligned rows).
#define LDS_STRIDE 136

__device__ __forceinline__ void stage_split(const float* __restrict__ G, int m0, int limit,
                                            const float* __restrict__ sdinv, bool scale,
                                            __nv_bfloat16* __restrict__ hi,
                                            __nv_bfloat16* __restrict__ lo, int tid) {
    for (int it = tid; it < 2048; it += 256) {
        int r = it >> 4, c = it & 15;       // row 0..127, 8-col chunk 0..15
        int m = m0 + r;
        float4 v0 = make_float4(0.f, 0.f, 0.f, 0.f), v1 = v0;
        if (m < limit) {
            const float4* g = reinterpret_cast<const float4*>(G + (size_t)m * FEAT + c * 8);
            v0 = __ldg(g);
            v1 = __ldg(g + 1);
        }
        float s = scale ? sdinv[r] : 1.f;
        float f[8] = {v0.x * s, v0.y * s, v0.z * s, v0.w * s,
                      v1.x * s, v1.y * s, v1.z * s, v1.w * s};
        uint32_t hw[4], lw[4];
#pragma unroll
        for (int j = 0; j < 4; j++) {
            __nv_bfloat16 h0 = __float2bfloat16(f[2 * j]);
            __nv_bfloat16 h1 = __float2bfloat16(f[2 * j + 1]);
            float r0 = f[2 * j]     - __bfloat162float(h0);
            float r1 = f[2 * j + 1] - __bfloat162float(h1);
            __nv_bfloat16 l0 = __float2bfloat16(r0);
            __nv_bfloat16 l1 = __float2bfloat16(r1);
            hw[j] = ((uint32_t)__bfloat16_as_ushort(h1) << 16) | __bfloat16_as_ushort(h0);
            lw[j] = ((uint32_t)__bfloat16_as_ushort(l1) << 16) | __bfloat16_as_ushort(l0);
        }
        int eoff = r * LDS_STRIDE + c * 8;          // 16B-aligned (272 = 16*17)
        *reinterpret_cast<uint4*>(hi + eoff) = make_uint4(hw[0], hw[1], hw[2], hw[3]);
        *reinterpret_cast<uint4*>(lo + eoff) = make_uint4(lw[0], lw[1], lw[2], lw[3]);
    }
}

// ---------------- tensor-core fused SAGE layer ----------------
// out = relu( (dinv*agg) @ Wl^T + x @ Wr^T + bl ) (+ res)
// 128x128 tile per block, 8 warps in 4(M) x 2(N), warp tile 32x64.
// split-bf16 3-term: Ah*Wh + Al*Wh + Ah*Wl.
#define SMEM_MMA (4 * 128 * LDS_STRIDE * 2)   // 139264 B

__global__ __launch_bounds__(256, 1)
void sage_gemm_mma(const float* __restrict__ Ain, const float* __restrict__ Xin,
                   const float* __restrict__ dinv,
                   const float* __restrict__ Wl, const float* __restrict__ bl,
                   const float* __restrict__ Wr,
                   const float* __restrict__ res, float* __restrict__ out) {
    extern __shared__ __align__(16) char smraw[];
    __nv_bfloat16* sAh = reinterpret_cast<__nv_bfloat16*>(smraw);
    __nv_bfloat16* sAl = sAh + 128 * LDS_STRIDE;
    __nv_bfloat16* sWh = sAl + 128 * LDS_STRIDE;
    __nv_bfloat16* sWl = sWh + 128 * LDS_STRIDE;
    __shared__ float s_dinv[128];
    __shared__ float s_bl[128];

    const int tid  = threadIdx.x;
    const int wid  = tid >> 5;
    const int lane = tid & 31;
    const int g    = lane >> 2;      // group id 0..7
    const int tg   = lane & 3;       // thread-in-group 0..3
    const int m0   = blockIdx.x * 128;
    const int m0w  = (wid & 3) * 32; // warp M offset
    const int n0w  = (wid >> 2) * 64;// warp N offset

    if (tid < 128) {
        int m = m0 + tid;
        s_dinv[tid] = (m < N_NODES) ? __ldg(dinv + m) : 0.f;
        s_bl[tid]   = __ldg(bl + tid);
    }
    __syncthreads();

    float acc[2][8][4];
#pragma unroll
    for (int mt = 0; mt < 2; mt++)
#pragma unroll
        for (int nt = 0; nt < 8; nt++)
#pragma unroll
            for (int q = 0; q < 4; q++) acc[mt][nt][q] = 0.f;

    for (int pass = 0; pass < 2; pass++) {
        if (pass) __syncthreads();   // previous-pass readers done before restage
        stage_split(pass ? Xin : Ain, m0, N_NODES, s_dinv, pass == 0, sAh, sAl, tid);
        stage_split(pass ? Wr : Wl, 0, 1 << 30, nullptr, false, sWh, sWl, tid);
        __syncthreads();

#pragma unroll
        for (int kk = 0; kk < 8; kk++) {
            const int k0 = kk * 16;
            uint32_t ah[2][4], al[2][4], bh[8][2], blo[8][2];
#pragma unroll
            for (int mt = 0; mt < 2; mt++) {
                int r0 = m0w + mt * 16 + g;
                int e0 = r0 * LDS_STRIDE + k0 + tg * 2;
                ah[mt][0] = *reinterpret_cast<const uint32_t*>(sAh + e0);
                ah[mt][1] = *reinterpret_cast<const uint32_t*>(sAh + e0 + 8 * LDS_STRIDE);
                ah[mt][2] = *reinterpret_cast<const uint32_t*>(sAh + e0 + 8);
                ah[mt][3] = *reinterpret_cast<const uint32_t*>(sAh + e0 + 8 * LDS_STRIDE + 8);
                al[mt][0] = *reinterpret_cast<const uint32_t*>(sAl + e0);
                al[mt][1] = *reinterpret_cast<const uint32_t*>(sAl + e0 + 8 * LDS_STRIDE);
                al[mt][2] = *reinterpret_cast<const uint32_t*>(sAl + e0 + 8);
                al[mt][3] = *reinterpret_cast<const uint32_t*>(sAl + e0 + 8 * LDS_STRIDE + 8);
            }
#pragma unroll
            for (int nt = 0; nt < 8; nt++) {
                int n = n0w + nt * 8 + g;
                int e0 = n * LDS_STRIDE + k0 + tg * 2;
                bh[nt][0]  = *reinterpret_cast<const uint32_t*>(sWh + e0);
                bh[nt][1]  = *reinterpret_cast<const uint32_t*>(sWh + e0 + 8);
                blo[nt][0] = *reinterpret_cast<const uint32_t*>(sWl + e0);
                blo[nt][1] = *reinterpret_cast<const uint32_t*>(sWl + e0 + 8);
            }
#pragma unroll
            for (int mt = 0; mt < 2; mt++)
#pragma unroll
                for (int nt = 0; nt < 8; nt++) {
                    mma_bf16(acc[mt][nt], ah[mt], bh[nt]);
                    mma_bf16(acc[mt][nt], al[mt], bh[nt]);
                    mma_bf16(acc[mt][nt], ah[mt], blo[nt]);
                }
        }
    }

    // epilogue: bias + relu (+ residual)
#pragma unroll
    for (int mt = 0; mt < 2; mt++) {
#pragma unroll
        for (int half = 0; half < 2; half++) {
            int m = m0 + m0w + mt * 16 + g + half * 8;
            if (m < N_NODES) {
#pragma unroll
                for (int nt = 0; nt < 8; nt++) {
                    int n = n0w + nt * 8 + tg * 2;
                    float2 v;
                    v.x = fmaxf(acc[mt][nt][half * 2 + 0] + s_bl[n], 0.f);
                    v.y = fmaxf(acc[mt][nt][half * 2 + 1] + s_bl[n + 1], 0.f);
                    if (res) {
                        float2 rv = *reinterpret_cast<const float2*>(res + (size_t)m * FEAT + n);
                        v.x += rv.x; v.y += rv.y;
                    }
                    *reinterpret_cast<float2*>(out + (size_t)m * FEAT + n) = v;
                }
            }
        }
    }
}

// ---------------- classifier (fp32, small) ----------------
#define PAD 129
#define SMEM_CLS ((128 * PAD + 40 * PAD) * (int)sizeof(float))

__global__ __launch_bounds__(256)
void classifier_k(const float* __restrict__ X,
                  const float* __restrict__ Wc,
                  const float* __restrict__ bc,
                  float* __restrict__ out) {
    extern __shared__ float smf[];
    float* sX = smf;
    float* sW = smf + 128 * PAD;

    const int tid  = threadIdx.x;
    const int warp = tid >> 5;
    const int lane = tid & 31;
    const int tx   = tid & 7;
    const int ty   = tid >> 3;
    const int m0   = blockIdx.x * 128;

    for (int r = warp; r < 128; r += 8) {
        int m = m0 + r;
        float4 v = make_float4(0.f, 0.f, 0.f, 0.f);
        if (m < N_NODES)
            v = __ldg(reinterpret_cast<const float4*>(X + (size_t)m * FEAT) + lane);
        float* row = sX + r * PAD + lane * 4;
        row[0] = v.x; row[1] = v.y; row[2] = v.z; row[3] = v.w;
    }
    for (int n = warp; n < N_CLS; n += 8) {
        float4 v = __ldg(reinterpret_cast<const float4*>(Wc + (size_t)n * FEAT) + lane);
        float* row = sW + n * PAD + lane * 4;
        row[0] = v.x; row[1] = v.y; row[2] = v.z; row[3] = v.w;
    }
    __syncthreads();

    float acc[4][5];
#pragma unroll
    for (int r = 0; r < 4; r++)
#pragma unroll
        for (int c = 0; c < 5; c++) acc[r][c] = 0.f;

#pragma unroll 4
    for (int k = 0; k < 128; k++) {
        float a[4], w[5];
#pragma unroll
        for (int r = 0; r < 4; r++) a[r] = sX[(ty * 4 + r) * PAD + k];
#pragma unroll
        for (int c = 0; c < 5; c++) w[c] = sW[(tx + 8 * c) * PAD + k];
#pragma unroll
        for (int r = 0; r < 4; r++)
#pragma unroll
            for (int c = 0; c < 5; c++)
                acc[r][c] = fmaf(a[r], w[c], acc[r][c]);
    }

#pragma unroll
    for (int r = 0; r < 4; r++) {
        int m = m0 + ty * 4 + r;
        if (m < N_NODES) {
#pragma unroll
            for (int c = 0; c < 5; c++) {
                int n = tx + 8 * c;
                out[(size_t)m * N_CLS + n] = acc[r][c] + __ldg(bc + n);
            }
        }
    }
}

// ---------------- launch ----------------
extern "C" void kernel_launch(void* const* d_in, const int* in_sizes, int n_in,
                              void* d_out, int out_size) {
    const float* x   = (const float*)d_in[0];
    const int*   ei  = (const int*)d_in[1];
    const float* Wl1 = (const float*)d_in[2];
    const float* bl1 = (const float*)d_in[3];
    const float* Wr1 = (const float*)d_in[4];
    const float* Wl2 = (const float*)d_in[5];
    const float* bl2 = (const float*)d_in[6];
    const float* Wr2 = (const float*)d_in[7];
    const float* Wl3 = (const float*)d_in[8];
    const float* bl3 = (const float*)d_in[9];
    const float* Wr3 = (const float*)d_in[10];
    const float* Wc  = (const float*)d_in[11];
    const float* bc  = (const float*)d_in[12];
    float* out = (float*)d_out;

    const int* src = ei;
    const int* dst = ei + N_EDGES;

    float *p_deg, *p_agg, *p_h1, *p_h2, *p_h3;
    cudaGetSymbolAddress((void**)&p_deg, g_deg);
    cudaGetSymbolAddress((void**)&p_agg, g_agg);
    cudaGetSymbolAddress((void**)&p_h1,  g_h1);
    cudaGetSymbolAddress((void**)&p_h2,  g_h2);
    cudaGetSymbolAddress((void**)&p_h3,  g_h3);

    cudaFuncSetAttribute(sage_gemm_mma, cudaFuncAttributeMaxDynamicSharedMemorySize, SMEM_MMA);
    cudaFuncSetAttribute(classifier_k,  cudaFuncAttributeMaxDynamicSharedMemorySize, SMEM_CLS);

    const int AGG4 = N_NODES * FEAT / 4;
    const int DEG4 = N_NODES / 4;
    const int scatter_blocks = (N_EDGES * 32 + 255) / 256;
    const int gemm_blocks    = (N_NODES + 127) / 128;
    const int cls_blocks     = (N_NODES + 127) / 128;

    // degree + inverse
    zero_buf<<<(DEG4 + 255) / 256, 256>>>((float4*)p_deg, DEG4);
    deg_count<<<(N_EDGES + 255) / 256, 256>>>(dst);
    deg_invert<<<(N_NODES + 255) / 256, 256>>>();

    // layer 1
    zero_buf<<<(AGG4 + 255) / 256, 256>>>((float4*)p_agg, AGG4);
    scatter_add<<<scatter_blocks, 256>>>(x, src, dst);
    sage_gemm_mma<<<gemm_blocks, 256, SMEM_MMA>>>(p_agg, x, p_deg, Wl1, bl1, Wr1, nullptr, p_h1);

    // layer 2
    zero_buf<<<(AGG4 + 255) / 256, 256>>>((float4*)p_agg, AGG4);
    scatter_add<<<scatter_blocks, 256>>>(p_h1, src, dst);
    sage_gemm_mma<<<gemm_blocks, 256, SMEM_MMA>>>(p_agg, p_h1, p_deg, Wl2, bl2, Wr2, nullptr, p_h2);

    // layer 3 + residual
    zero_buf<<<(AGG4 + 255) / 256, 256>>>((float4*)p_agg, AGG4);
    scatter_add<<<scatter_blocks, 256>>>(p_h2, src, dst);
    sage_gemm_mma<<<gemm_blocks, 256, SMEM_MMA>>>(p_agg, p_h2, p_deg, Wl3, bl3, Wr3, p_h2, p_h3);

    // classifier
    classifier_k<<<cls_blocks, 256, SMEM_CLS>>>(p_h3, Wc, bc, out);
}

// round 4
// speedup vs baseline: 2.1370x; 1.4971x over previous
#include <cuda_runtime.h>
#include <cuda_bf16.h>
#include <cstdint>

#define N_NODES 50000
#define N_EDGES 600000
#define FEAT    128
#define N_CLS   40
#define SCAN_BLOCKS 196   // ceil(50000/256)

// ---------------- scratch (no allocations allowed) ----------------
__device__ float g_dinv[N_NODES];
__device__ int   g_degi[N_NODES];
__device__ int   g_rowptr[N_NODES];
__device__ int   g_cursor[N_NODES];
__device__ int   g_esrc[N_EDGES];
__device__ int   g_bsum[SCAN_BLOCKS];
__device__ float g_agg[N_NODES * FEAT];
__device__ float g_h1[N_NODES * FEAT];
__device__ float g_h2[N_NODES * FEAT];
__device__ float g_h3[N_NODES * FEAT];

// ---------------- CSR build ----------------
__global__ void zero_degi() {
    int i = blockIdx.x * blockDim.x + threadIdx.x;
    if (i < N_NODES) g_degi[i] = 0;
}

__global__ void deg_count_i(const int* __restrict__ dst) {
    int e = blockIdx.x * blockDim.x + threadIdx.x;
    if (e < N_EDGES) atomicAdd(&g_degi[dst[e]], 1);
}

__global__ void scan_part() {   // per-block sums of degi
    __shared__ int red[256];
    int i = blockIdx.x * 256 + threadIdx.x;
    int v = (i < N_NODES) ? g_degi[i] : 0;
    red[threadIdx.x] = v;
    __syncthreads();
    for (int s = 128; s > 0; s >>= 1) {
        if (threadIdx.x < s) red[threadIdx.x] += red[threadIdx.x + s];
        __syncthreads();
    }
    if (threadIdx.x == 0) g_bsum[blockIdx.x] = red[0];
}

__global__ void scan_top() {    // exclusive scan of g_bsum (<=256 entries), 1 block 256 thr
    int t = threadIdx.x;
    int lane = t & 31, wid = t >> 5;
    int v = (t < SCAN_BLOCKS) ? g_bsum[t] : 0;
    int inc = v;
#pragma unroll
    for (int d = 1; d < 32; d <<= 1) {
        int u = __shfl_up_sync(0xffffffffu, inc, d);
        if (lane >= d) inc += u;
    }
    __shared__ int wsum[8];
    if (lane == 31) wsum[wid] = inc;
    __syncthreads();
    if (wid == 0 && lane < 8) {
        int w = wsum[lane];
        int winc = w;
#pragma unroll
        for (int d = 1; d < 8; d <<= 1) {
            int u = __shfl_up_sync(0xffu, winc, d);
            if (lane >= d) winc += u;
        }
        wsum[lane] = winc - w;   // exclusive warp offset
    }
    __syncthreads();
    if (t < SCAN_BLOCKS) g_bsum[t] = inc - v + wsum[wid];
}

__global__ void scan_final() {  // rowptr/cursor = exclusive scan + block offset; dinv
    int t = threadIdx.x;
    int lane = t & 31, wid = t >> 5;
    int i = blockIdx.x * 256 + t;
    int v = (i < N_NODES) ? g_degi[i] : 0;
    int inc = v;
#pragma unroll
    for (int d = 1; d < 32; d <<= 1) {
        int u = __shfl_up_sync(0xffffffffu, inc, d);
        if (lane >= d) inc += u;
    }
    __shared__ int wsum[8];
    if (lane == 31) wsum[wid] = inc;
    __syncthreads();
    if (wid == 0 && lane < 8) {
        int w = wsum[lane];
        int winc = w;
#pragma unroll
        for (int d = 1; d < 8; d <<= 1) {
            int u = __shfl_up_sync(0xffu, winc, d);
            if (lane >= d) winc += u;
        }
        wsum[lane] = winc - w;
    }
    __syncthreads();
    if (i < N_NODES) {
        int excl = inc - v + wsum[wid] + g_bsum[blockIdx.x];
        g_rowptr[i] = excl;
        g_cursor[i] = excl;
        g_dinv[i]   = 1.0f / fmaxf((float)v, 1.0f);
    }
}

__global__ void bucket_edges(const int* __restrict__ src, const int* __restrict__ dst) {
    int e = blockIdx.x * blockDim.x + threadIdx.x;
    if (e < N_EDGES) {
        int d = dst[e];
        int pos = atomicAdd(&g_cursor[d], 1);
        g_esrc[pos] = src[e];
    }
}

// ---------------- CSR mean-gather: one warp per node ----------------
__global__ __launch_bounds__(256)
void gather_mean(const float* __restrict__ X) {
    int wid  = (blockIdx.x * blockDim.x + threadIdx.x) >> 5;
    int lane = threadIdx.x & 31;
    if (wid >= N_NODES) return;
    int start = g_rowptr[wid];
    int deg   = g_degi[wid];
    float4 acc = make_float4(0.f, 0.f, 0.f, 0.f);
    int j = 0;
    for (; j + 4 <= deg; j += 4) {
        int s0 = __ldg(g_esrc + start + j);
        int s1 = __ldg(g_esrc + start + j + 1);
        int s2 = __ldg(g_esrc + start + j + 2);
        int s3 = __ldg(g_esrc + start + j + 3);
        float4 v0 = __ldg(reinterpret_cast<const float4*>(X + (size_t)s0 * FEAT) + lane);
        float4 v1 = __ldg(reinterpret_cast<const float4*>(X + (size_t)s1 * FEAT) + lane);
        float4 v2 = __ldg(reinterpret_cast<const float4*>(X + (size_t)s2 * FEAT) + lane);
        float4 v3 = __ldg(reinterpret_cast<const float4*>(X + (size_t)s3 * FEAT) + lane);
        acc.x += v0.x + v1.x + v2.x + v3.x;
        acc.y += v0.y + v1.y + v2.y + v3.y;
        acc.z += v0.z + v1.z + v2.z + v3.z;
        acc.w += v0.w + v1.w + v2.w + v3.w;
    }
    for (; j < deg; j++) {
        int s = __ldg(g_esrc + start + j);
        float4 v = __ldg(reinterpret_cast<const float4*>(X + (size_t)s * FEAT) + lane);
        acc.x += v.x; acc.y += v.y; acc.z += v.z; acc.w += v.w;
    }
    float di = g_dinv[wid];
    acc.x *= di; acc.y *= di; acc.z *= di; acc.w *= di;
    reinterpret_cast<float4*>(g_agg + (size_t)wid * FEAT)[lane] = acc;
}

// ---------------- mma.sync bf16 + ldmatrix (baseline PTX) ----------------
__device__ __forceinline__ void mma_bf16(float* c, const uint32_t* a, uint32_t b0, uint32_t b1) {
    asm volatile(
        "mma.sync.aligned.m16n8k16.row.col.f32.bf16.bf16.f32 "
        "{%0,%1,%2,%3}, {%4,%5,%6,%7}, {%8,%9}, {%0,%1,%2,%3};"
        : "+f"(c[0]), "+f"(c[1]), "+f"(c[2]), "+f"(c[3])
        : "r"(a[0]), "r"(a[1]), "r"(a[2]), "r"(a[3]), "r"(b0), "r"(b1));
}

#define LDMX4(R, addr) \
    asm volatile("ldmatrix.sync.aligned.m8n8.x4.shared.b16 {%0,%1,%2,%3}, [%4];" \
        : "=r"((R)[0]), "=r"((R)[1]), "=r"((R)[2]), "=r"((R)[3]) : "r"(addr))

__device__ __forceinline__ uint32_t smem_u32(const void* p) {
    uint32_t a;
    asm("{ .reg .u64 t; cvta.to.shared.u64 t, %1; cvt.u32.u64 %0, t; }" : "=r"(a) : "l"(p));
    return a;
}

// ---------------- fp32 -> split bf16 (hi/lo) staging ----------------
#define LDS_STRIDE 136   // 272B rows = 17 x 16B (odd -> ldmatrix conflict-free)

__device__ __forceinline__ void stage_split(const float* __restrict__ G, int m0, int limit,
                                            __nv_bfloat16* __restrict__ hi,
                                            __nv_bfloat16* __restrict__ lo, int tid) {
    for (int it = tid; it < 2048; it += 256) {
        int r = it >> 4, c = it & 15;
        int m = m0 + r;
        float4 v0 = make_float4(0.f, 0.f, 0.f, 0.f), v1 = v0;
        if (m < limit) {
            const float4* g = reinterpret_cast<const float4*>(G + (size_t)m * FEAT + c * 8);
            v0 = __ldg(g);
            v1 = __ldg(g + 1);
        }
        float f[8] = {v0.x, v0.y, v0.z, v0.w, v1.x, v1.y, v1.z, v1.w};
        uint32_t hw[4], lw[4];
#pragma unroll
        for (int j = 0; j < 4; j++) {
            __nv_bfloat16 h0 = __float2bfloat16(f[2 * j]);
            __nv_bfloat16 h1 = __float2bfloat16(f[2 * j + 1]);
            float r0 = f[2 * j]     - __bfloat162float(h0);
            float r1 = f[2 * j + 1] - __bfloat162float(h1);
            __nv_bfloat16 l0 = __float2bfloat16(r0);
            __nv_bfloat16 l1 = __float2bfloat16(r1);
            hw[j] = ((uint32_t)__bfloat16_as_ushort(h1) << 16) | __bfloat16_as_ushort(h0);
            lw[j] = ((uint32_t)__bfloat16_as_ushort(l1) << 16) | __bfloat16_as_ushort(l0);
        }
        int eoff = r * LDS_STRIDE + c * 8;
        *reinterpret_cast<uint4*>(hi + eoff) = make_uint4(hw[0], hw[1], hw[2], hw[3]);
        *reinterpret_cast<uint4*>(lo + eoff) = make_uint4(lw[0], lw[1], lw[2], lw[3]);
    }
}

// ---------------- tensor-core fused SAGE layer ----------------
// out = relu( aggm @ Wl^T + x @ Wr^T + bl ) (+ res)   [aggm already mean-scaled]
#define SMEM_MMA (4 * 128 * LDS_STRIDE * 2)   // 139264 B

__global__ __launch_bounds__(256, 1)
void sage_gemm_mma(const float* __restrict__ Ain, const float* __restrict__ Xin,
                   const float* __restrict__ Wl, const float* __restrict__ bl,
                   const float* __restrict__ Wr,
                   const float* __restrict__ res, float* __restrict__ out) {
    extern __shared__ __align__(16) char smraw[];
    __nv_bfloat16* sAh = reinterpret_cast<__nv_bfloat16*>(smraw);
    __nv_bfloat16* sAl = sAh + 128 * LDS_STRIDE;
    __nv_bfloat16* sWh = sAl + 128 * LDS_STRIDE;
    __nv_bfloat16* sWl = sWh + 128 * LDS_STRIDE;
    __shared__ float s_bl[128];

    const int tid  = threadIdx.x;
    const int wid  = tid >> 5;
    const int lane = tid & 31;
    const int g    = lane >> 2;
    const int tg   = lane & 3;
    const int m0   = blockIdx.x * 128;
    const int m0w  = (wid & 3) * 32;
    const int n0w  = (wid >> 2) * 64;

    if (tid < 128) s_bl[tid] = __ldg(bl + tid);

    // per-lane ldmatrix byte offsets (within a tile at row base 0, k base 0)
    const uint32_t aoff = (uint32_t)(((lane & 15) * LDS_STRIDE + (lane >> 4) * 8) * 2);
    const uint32_t boff = (uint32_t)((((lane & 7) + ((lane >> 4) << 3)) * LDS_STRIDE
                                      + ((lane >> 3) & 1) * 8) * 2);
    const uint32_t uAh = smem_u32(sAh), uAl = smem_u32(sAl);
    const uint32_t uWh = smem_u32(sWh), uWl = smem_u32(sWl);

    float acc[2][8][4];
#pragma unroll
    for (int mt = 0; mt < 2; mt++)
#pragma unroll
        for (int nt = 0; nt < 8; nt++)
#pragma unroll
            for (int q = 0; q < 4; q++) acc[mt][nt][q] = 0.f;

    for (int pass = 0; pass < 2; pass++) {
        if (pass) __syncthreads();
        stage_split(pass ? Xin : Ain, m0, N_NODES, sAh, sAl, tid);
        stage_split(pass ? Wr : Wl, 0, 1 << 30, sWh, sWl, tid);
        __syncthreads();

#pragma unroll
        for (int kk = 0; kk < 8; kk++) {
            const uint32_t kB = kk * 32;   // 16 bf16 = 32 bytes
            uint32_t ah[2][4], al[2][4], bh[4][4], blo[4][4];
#pragma unroll
            for (int mt = 0; mt < 2; mt++) {
                uint32_t rb = (uint32_t)((m0w + mt * 16) * LDS_STRIDE * 2) + kB + aoff;
                LDMX4(ah[mt], uAh + rb);
                LDMX4(al[mt], uAl + rb);
            }
#pragma unroll
            for (int p = 0; p < 4; p++) {
                uint32_t rb = (uint32_t)((n0w + p * 16) * LDS_STRIDE * 2) + kB + boff;
                LDMX4(bh[p],  uWh + rb);
                LDMX4(blo[p], uWl + rb);
            }
#pragma unroll
            for (int mt = 0; mt < 2; mt++)
#pragma unroll
                for (int nt = 0; nt < 8; nt++) {
                    int p = nt >> 1, s = (nt & 1) * 2;
                    mma_bf16(acc[mt][nt], ah[mt], bh[p][s], bh[p][s + 1]);
                    mma_bf16(acc[mt][nt], al[mt], bh[p][s], bh[p][s + 1]);
                    mma_bf16(acc[mt][nt], ah[mt], blo[p][s], blo[p][s + 1]);
                }
        }
    }

    // epilogue: bias + relu (+ residual)
#pragma unroll
    for (int mt = 0; mt < 2; mt++) {
#pragma unroll
        for (int half = 0; half < 2; half++) {
            int m = m0 + m0w + mt * 16 + g + half * 8;
            if (m < N_NODES) {
#pragma unroll
                for (int nt = 0; nt < 8; nt++) {
                    int n = n0w + nt * 8 + tg * 2;
                    float2 v;
                    v.x = fmaxf(acc[mt][nt][half * 2 + 0] + s_bl[n], 0.f);
                    v.y = fmaxf(acc[mt][nt][half * 2 + 1] + s_bl[n + 1], 0.f);
                    if (res) {
                        float2 rv = *reinterpret_cast<const float2*>(res + (size_t)m * FEAT + n);
                        v.x += rv.x; v.y += rv.y;
                    }
                    *reinterpret_cast<float2*>(out + (size_t)m * FEAT + n) = v;
                }
            }
        }
    }
}

// ---------------- classifier (fp32, small) ----------------
#define PAD 129
#define SMEM_CLS ((128 * PAD + 40 * PAD) * (int)sizeof(float))

__global__ __launch_bounds__(256)
void classifier_k(const float* __restrict__ X,
                  const float* __restrict__ Wc,
                  const float* __restrict__ bc,
                  float* __restrict__ out) {
    extern __shared__ float smf[];
    float* sX = smf;
    float* sW = smf + 128 * PAD;

    const int tid  = threadIdx.x;
    const int warp = tid >> 5;
    const int lane = tid & 31;
    const int tx   = tid & 7;
    const int ty   = tid >> 3;
    const int m0   = blockIdx.x * 128;

    for (int r = warp; r < 128; r += 8) {
        int m = m0 + r;
        float4 v = make_float4(0.f, 0.f, 0.f, 0.f);
        if (m < N_NODES)
            v = __ldg(reinterpret_cast<const float4*>(X + (size_t)m * FEAT) + lane);
        float* row = sX + r * PAD + lane * 4;
        row[0] = v.x; row[1] = v.y; row[2] = v.z; row[3] = v.w;
    }
    for (int n = warp; n < N_CLS; n += 8) {
        float4 v = __ldg(reinterpret_cast<const float4*>(Wc + (size_t)n * FEAT) + lane);
        float* row = sW + n * PAD + lane * 4;
        row[0] = v.x; row[1] = v.y; row[2] = v.z; row[3] = v.w;
    }
    __syncthreads();

    float acc[4][5];
#pragma unroll
    for (int r = 0; r < 4; r++)
#pragma unroll
        for (int c = 0; c < 5; c++) acc[r][c] = 0.f;

#pragma unroll 4
    for (int k = 0; k < 128; k++) {
        float a[4], w[5];
#pragma unroll
        for (int r = 0; r < 4; r++) a[r] = sX[(ty * 4 + r) * PAD + k];
#pragma unroll
        for (int c = 0; c < 5; c++) w[c] = sW[(tx + 8 * c) * PAD + k];
#pragma unroll
        for (int r = 0; r < 4; r++)
#pragma unroll
            for (int c = 0; c < 5; c++)
                acc[r][c] = fmaf(a[r], w[c], acc[r][c]);
    }

#pragma unroll
    for (int r = 0; r < 4; r++) {
        int m = m0 + ty * 4 + r;
        if (m < N_NODES) {
#pragma unroll
            for (int c = 0; c < 5; c++) {
                int n = tx + 8 * c;
                out[(size_t)m * N_CLS + n] = acc[r][c] + __ldg(bc + n);
            }
        }
    }
}

// ---------------- launch ----------------
extern "C" void kernel_launch(void* const* d_in, const int* in_sizes, int n_in,
                              void* d_out, int out_size) {
    const float* x   = (const float*)d_in[0];
    const int*   ei  = (const int*)d_in[1];
    const float* Wl1 = (const float*)d_in[2];
    const float* bl1 = (const float*)d_in[3];
    const float* Wr1 = (const float*)d_in[4];
    const float* Wl2 = (const float*)d_in[5];
    const float* bl2 = (const float*)d_in[6];
    const float* Wr2 = (const float*)d_in[7];
    const float* Wl3 = (const float*)d_in[8];
    const float* bl3 = (const float*)d_in[9];
    const float* Wr3 = (const float*)d_in[10];
    const float* Wc  = (const float*)d_in[11];
    const float* bc  = (const float*)d_in[12];
    float* out = (float*)d_out;

    const int* src = ei;
    const int* dst = ei + N_EDGES;

    float *p_agg, *p_h1, *p_h2, *p_h3;
    cudaGetSymbolAddress((void**)&p_agg, g_agg);
    cudaGetSymbolAddress((void**)&p_h1,  g_h1);
    cudaGetSymbolAddress((void**)&p_h2,  g_h2);
    cudaGetSymbolAddress((void**)&p_h3,  g_h3);

    cudaFuncSetAttribute(sage_gemm_mma, cudaFuncAttributeMaxDynamicSharedMemorySize, SMEM_MMA);
    cudaFuncSetAttribute(classifier_k,  cudaFuncAttributeMaxDynamicSharedMemorySize, SMEM_CLS);

    const int edge_blocks   = (N_EDGES + 255) / 256;
    const int gather_blocks = (N_NODES * 32 + 255) / 256;
    const int gemm_blocks   = (N_NODES + 127) / 128;
    const int cls_blocks    = (N_NODES + 127) / 128;

    // ---- CSR build (once; reused by all 3 layers) ----
    zero_degi<<<(N_NODES + 255) / 256, 256>>>();
    deg_count_i<<<edge_blocks, 256>>>(dst);
    scan_part<<<SCAN_BLOCKS, 256>>>();
    scan_top<<<1, 256>>>();
    scan_final<<<SCAN_BLOCKS, 256>>>();
    bucket_edges<<<edge_blocks, 256>>>(src, dst);

    // layer 1
    gather_mean<<<gather_blocks, 256>>>(x);
    sage_gemm_mma<<<gemm_blocks, 256, SMEM_MMA>>>(p_agg, x, Wl1, bl1, Wr1, nullptr, p_h1);

    // layer 2
    gather_mean<<<gather_blocks, 256>>>(p_h1);
    sage_gemm_mma<<<gemm_blocks, 256, SMEM_MMA>>>(p_agg, p_h1, Wl2, bl2, Wr2, nullptr, p_h2);

    // layer 3 + residual
    gather_mean<<<gather_blocks, 256>>>(p_h2);
    sage_gemm_mma<<<gemm_blocks, 256, SMEM_MMA>>>(p_agg, p_h2, Wl3, bl3, Wr3, p_h2, p_h3);

    // classifier
    classifier_k<<<cls_blocks, 256, SMEM_CLS>>>(p_h3, Wc, bc, out);
}